// round 14
// baseline (speedup 1.0000x reference)
#include <cuda_runtime.h>
#include <cuda_bf16.h>
#include <cstdint>

// Problem constants
#define BB 4
#define LL 2048
#define EE 1024
#define HH 16
#define DD 64
#define MM (BB * LL)   // 8192 rows

// Scratch (allocation-free rule: __device__ globals)
__device__ float g_QKV[3 * MM * EE];                 // Q,K key-major; V d-major [B][E][L]
__device__ __nv_bfloat16 g_Ah[MM * EE];              // x-split, then O-split
__device__ __nv_bfloat16 g_Al[MM * EE];
__device__ __nv_bfloat16 g_Wh[4 * EE * EE];          // Wq,Wk,Wv,Wo hi
__device__ __nv_bfloat16 g_Wl[4 * EE * EE];          // lo

// ----------------------------------------------------------------------------
// helpers
// ----------------------------------------------------------------------------
__device__ __forceinline__ uint32_t f2tf32(float a) {
    uint32_t r;
    asm("cvt.rna.tf32.f32 %0, %1;" : "=r"(r) : "f"(a));
    return r;
}
__device__ __forceinline__ float f2tf32f(float a) {
    return __uint_as_float(f2tf32(a));
}
__device__ __forceinline__ float ex2f(float x) {
    float r;
    asm("ex2.approx.ftz.f32 %0, %1;" : "=f"(r) : "f"(x));
    return r;
}

__device__ __forceinline__ void mma_tf32_m16n8k8(
    float d[4], uint32_t a0, uint32_t a1, uint32_t a2, uint32_t a3,
    uint32_t b0, uint32_t b1)
{
    asm volatile(
        "mma.sync.aligned.m16n8k8.row.col.f32.tf32.tf32.f32 "
        "{%0,%1,%2,%3}, {%4,%5,%6,%7}, {%8,%9}, {%0,%1,%2,%3};"
        : "+f"(d[0]), "+f"(d[1]), "+f"(d[2]), "+f"(d[3])
        : "r"(a0), "r"(a1), "r"(a2), "r"(a3), "r"(b0), "r"(b1));
}

__device__ __forceinline__ void mma_bf16_m16n8k16(
    float d[4], uint32_t a0, uint32_t a1, uint32_t a2, uint32_t a3,
    uint32_t b0, uint32_t b1)
{
    asm volatile(
        "mma.sync.aligned.m16n8k16.row.col.f32.bf16.bf16.f32 "
        "{%0,%1,%2,%3}, {%4,%5,%6,%7}, {%8,%9}, {%0,%1,%2,%3};"
        : "+f"(d[0]), "+f"(d[1]), "+f"(d[2]), "+f"(d[3])
        : "r"(a0), "r"(a1), "r"(a2), "r"(a3), "r"(b0), "r"(b1));
}

#define LDSM4(r0, r1, r2, r3, addr) \
    asm volatile("ldmatrix.sync.aligned.m8n8.x4.shared.b16 {%0,%1,%2,%3}, [%4];" \
                 : "=r"(r0), "=r"(r1), "=r"(r2), "=r"(r3) : "r"(addr))

__device__ __forceinline__ void cp16(uint32_t smem_dst, const void* gsrc) {
    asm volatile("cp.async.cg.shared.global [%0], [%1], 16;\n"
                 :: "r"(smem_dst), "l"(gsrc));
}
__device__ __forceinline__ void cp_commit() {
    asm volatile("cp.async.commit_group;\n");
}
template <int N> __device__ __forceinline__ void cp_wait() {
    asm volatile("cp.async.wait_group %0;\n" :: "n"(N));
}
__device__ __forceinline__ uint32_t smem_u32(const void* p) {
    return (uint32_t)__cvta_generic_to_shared(p);
}

// ----------------------------------------------------------------------------
// Elementwise split fp32 -> (bf16 hi, bf16 lo). n2 = element count / 2.
// ----------------------------------------------------------------------------
__global__ __launch_bounds__(256) void split_bf16(
    const float2* __restrict__ in, __nv_bfloat162* __restrict__ hi,
    __nv_bfloat162* __restrict__ lo, int n2)
{
    int i = blockIdx.x * blockDim.x + threadIdx.x;
    if (i >= n2) return;
    float2 v = in[i];
    __nv_bfloat16 hx = __float2bfloat16(v.x);
    __nv_bfloat16 hy = __float2bfloat16(v.y);
    __nv_bfloat16 lx = __float2bfloat16(v.x - __bfloat162float(hx));
    __nv_bfloat16 ly = __float2bfloat16(v.y - __bfloat162float(hy));
    hi[i] = __nv_bfloat162{hx, hy};
    lo[i] = __nv_bfloat162{lx, ly};
}

// ----------------------------------------------------------------------------
// Split + transpose all 4 weights: W fp32 [K][N] -> hi/lo bf16 [N][K].
// ----------------------------------------------------------------------------
__global__ __launch_bounds__(256) void split_w4(
    const float* __restrict__ W0, const float* __restrict__ W1,
    const float* __restrict__ W2, const float* __restrict__ W3,
    __nv_bfloat16* __restrict__ hi, __nv_bfloat16* __restrict__ lo,
    int K, int N)
{
    __shared__ float tile[32][33];
    const int z = blockIdx.z;
    const float* in = (z == 0) ? W0 : (z == 1) ? W1 : (z == 2) ? W2 : W3;
    __nv_bfloat16* hz = hi + (size_t)z * K * N;
    __nv_bfloat16* lz = lo + (size_t)z * K * N;

    const int k0 = blockIdx.y * 32;
    const int n0 = blockIdx.x * 32;
    const int tx = threadIdx.x & 31;
    const int ty = threadIdx.x >> 5;   // 0..7

    #pragma unroll
    for (int p = 0; p < 4; p++)
        tile[ty + p * 8][tx] = in[(size_t)(k0 + ty + p * 8) * N + n0 + tx];
    __syncthreads();

    #pragma unroll
    for (int p = 0; p < 4; p++) {
        const int n = n0 + ty + p * 8;
        float v = tile[tx][ty + p * 8];
        __nv_bfloat16 h = __float2bfloat16(v);
        __nv_bfloat16 l = __float2bfloat16(v - __bfloat162float(h));
        hz[(size_t)n * K + k0 + tx] = h;
        lz[(size_t)n * K + k0 + tx] = l;
    }
}

// ----------------------------------------------------------------------------
// bf16x3 GEMM: BK=32, 2-stage cp.async, LDSM fragments, 2 CTAs/SM.
// If sel == tsel, C slice is written TRANSPOSED as [B][N][L] (d-major V).
// ----------------------------------------------------------------------------
#define GLDB 40                         // smem row stride bf16 (32 + 8 pad)
#define STAGE_B (4 * 128 * GLDB)        // bf16 elems/stage = 20480 (40,960 B)

__global__ __launch_bounds__(256, 2) void gemm_bf16x3(
    const __nv_bfloat16* __restrict__ Ah, const __nv_bfloat16* __restrict__ Al,
    const __nv_bfloat16* __restrict__ Wh, const __nv_bfloat16* __restrict__ Wl,
    const float* __restrict__ bias, float* __restrict__ C,
    int M, int N, int K, int nblk, int tsel)
{
    extern __shared__ __nv_bfloat16 gsmb[];
    const uint32_t smbase = smem_u32(gsmb);

    const int tid  = threadIdx.x;
    const int lane = tid & 31;
    const int wid  = tid >> 5;
    const int wm   = (wid >> 2) * 64;
    const int wn   = (wid & 3) * 32;
    const int g    = lane >> 2;
    const int t    = lane & 3;

    const int sel = blockIdx.x / nblk;
    const int n0  = (blockIdx.x - sel * nblk) * 128;
    const int m0  = blockIdx.y * 128;

    const __nv_bfloat16* Bh = Wh + (size_t)sel * N * K;
    const __nv_bfloat16* Bl = Wl + (size_t)sel * N * K;
    float* Cs = C + (size_t)sel * M * N;

    const int aRow = wm + (lane & 7) + ((lane >> 3) & 1) * 8;
    const int aCol = (lane >> 4) * 8;
    const int bRow = wn + (lane & 7) + (lane >> 4) * 8;
    const int bCol = ((lane >> 3) & 1) * 8;

    float acc[4][4][4];
    #pragma unroll
    for (int i = 0; i < 4; i++)
        #pragma unroll
        for (int j = 0; j < 4; j++)
            #pragma unroll
            for (int r = 0; r < 4; r++) acc[i][j][r] = 0.0f;

    const int lr = tid >> 2;          // 0..63 (2 passes of 64 rows)
    const int lc = (tid & 3) * 8;     // bf16 col of 16B chunk

    auto load_stage = [&](int stage, int k0) {
        const uint32_t s0 = smbase + stage * STAGE_B * 2;
        const uint32_t aH = s0;
        const uint32_t aL = s0 + 128 * GLDB * 2;
        const uint32_t bH = s0 + 2 * 128 * GLDB * 2;
        const uint32_t bL = bH + 128 * GLDB * 2;
        #pragma unroll
        for (int p = 0; p < 2; p++) {
            const int r = lr + p * 64;
            const uint32_t so = (r * GLDB + lc) * 2;
            const size_t ga = (size_t)(m0 + r) * K + k0 + lc;
            cp16(aH + so, Ah + ga);
            cp16(aL + so, Al + ga);
            const size_t gb = (size_t)(n0 + r) * K + k0 + lc;
            cp16(bH + so, Bh + gb);
            cp16(bL + so, Bl + gb);
        }
        cp_commit();
    };

    load_stage(0, 0);

    const int ntiles = K / 32;
    for (int kt = 0; kt < ntiles; kt++) {
        if (kt + 1 < ntiles) {
            load_stage((kt + 1) & 1, (kt + 1) * 32);
            cp_wait<1>();
        } else {
            cp_wait<0>();
        }
        __syncthreads();

        const uint32_t sSt = smbase + (kt & 1) * STAGE_B * 2;
        const uint32_t sAh = sSt;
        const uint32_t sAl = sSt + 128 * GLDB * 2;
        const uint32_t sBh = sSt + 2 * 128 * GLDB * 2;
        const uint32_t sBl = sBh + 128 * GLDB * 2;

        #pragma unroll
        for (int ks = 0; ks < 2; ks++) {
            const int kk = ks * 16;
            uint32_t ah[4][4], al[4][4];
            #pragma unroll
            for (int mt = 0; mt < 4; mt++) {
                const uint32_t off = ((aRow + mt * 16) * GLDB + kk + aCol) * 2;
                LDSM4(ah[mt][0], ah[mt][1], ah[mt][2], ah[mt][3], sAh + off);
                LDSM4(al[mt][0], al[mt][1], al[mt][2], al[mt][3], sAl + off);
            }
            uint32_t bh[4][2], bl[4][2];
            #pragma unroll
            for (int p = 0; p < 2; p++) {
                const uint32_t off = ((bRow + p * 16) * GLDB + kk + bCol) * 2;
                LDSM4(bh[2 * p][0], bh[2 * p][1], bh[2 * p + 1][0], bh[2 * p + 1][1],
                      sBh + off);
                LDSM4(bl[2 * p][0], bl[2 * p][1], bl[2 * p + 1][0], bl[2 * p + 1][1],
                      sBl + off);
            }
            #pragma unroll
            for (int mt = 0; mt < 4; mt++)
                #pragma unroll
                for (int nt = 0; nt < 4; nt++) {
                    mma_bf16_m16n8k16(acc[mt][nt], al[mt][0], al[mt][1], al[mt][2], al[mt][3],
                                      bh[nt][0], bh[nt][1]);
                    mma_bf16_m16n8k16(acc[mt][nt], ah[mt][0], ah[mt][1], ah[mt][2], ah[mt][3],
                                      bl[nt][0], bl[nt][1]);
                    mma_bf16_m16n8k16(acc[mt][nt], ah[mt][0], ah[mt][1], ah[mt][2], ah[mt][3],
                                      bh[nt][0], bh[nt][1]);
                }
        }
        __syncthreads();
    }

    // Epilogue
    if (sel == tsel) {
        // transposed store: Cs treated as [B][N][L]
        #pragma unroll
        for (int mt = 0; mt < 4; mt++) {
            const int rr = m0 + wm + mt * 16 + g;
            const int bi = rr >> 11;            // rr / LL
            const int l  = rr & 2047;           // rr % LL
            float* Vt = Cs + (size_t)bi * EE * LL;
            #pragma unroll
            for (int nt = 0; nt < 4; nt++) {
                const int c = n0 + wn + nt * 8 + 2 * t;
                Vt[(size_t)c * LL + l]           = acc[mt][nt][0];
                Vt[(size_t)(c + 1) * LL + l]     = acc[mt][nt][1];
                Vt[(size_t)c * LL + l + 8]       = acc[mt][nt][2];
                Vt[(size_t)(c + 1) * LL + l + 8] = acc[mt][nt][3];
            }
        }
    } else {
        #pragma unroll
        for (int mt = 0; mt < 4; mt++) {
            const int r0 = m0 + wm + mt * 16 + g;
            #pragma unroll
            for (int nt = 0; nt < 4; nt++) {
                const int c = n0 + wn + nt * 8 + 2 * t;
                float b0 = bias ? bias[c]     : 0.0f;
                float b1 = bias ? bias[c + 1] : 0.0f;
                *(float2*)&Cs[(size_t)r0 * N + c] =
                    make_float2(acc[mt][nt][0] + b0, acc[mt][nt][1] + b1);
                *(float2*)&Cs[(size_t)(r0 + 8) * N + c] =
                    make_float2(acc[mt][nt][2] + b0, acc[mt][nt][3] + b1);
            }
        }
    }
}

// ----------------------------------------------------------------------------
// Flash attention, tf32 MMAs; Q/K AND V fragments via ldmatrix.
// V arrives d-major ([B][E][L], produced transposed by the QKV GEMM), so its
// smem tile is Vt[d][key] and PV B-fragments are plain non-trans ldmatrix.
// Fixed-max softmax (energies bounded), log2-domain exp. No P smem.
// ----------------------------------------------------------------------------
#define FQLD 68
#define FKLD 68
#define FVLDT 68

__global__ __launch_bounds__(256, 2) void flash_mma(
    const float* __restrict__ Q, const float* __restrict__ Kg,
    const float* __restrict__ Vt,
    __nv_bfloat16* __restrict__ Oh, __nv_bfloat16* __restrict__ Ol)
{
    extern __shared__ float sm[];
    float* Qs  = sm;                         // [128][FQLD]
    float* Ksb = Qs + 128 * FQLD;            // 2 x [64][FKLD]   key-major
    float* Vsb = Ksb + 2 * 64 * FKLD;        // 2 x [64][FVLDT]  d-major
    const uint32_t smQs = smem_u32(Qs);
    const uint32_t smKs = smem_u32(Ksb);
    const uint32_t smVs = smem_u32(Vsb);

    const int tid  = threadIdx.x;
    const int lane = tid & 31;
    const int wid  = tid >> 5;
    const int g    = lane >> 2;
    const int t    = lane & 3;
    const int qw   = wid * 16;

    // ldmatrix lane address components
    const int r8  = lane & 7;
    const int sub = lane >> 3;                // 0..3 (matrix index)
    const uint32_t qA = smQs + ((qw + r8 + (sub & 1) * 8) * FQLD + (sub >> 1) * 4) * 4;
    const uint32_t kRowOff = ((r8 + (sub >> 1) * 8) * FKLD + (sub & 1) * 4) * 4;
    // V (d-major): matrix sub at d-row (sub>>1)*8 + r8, key col (sub&1)*4
    const uint32_t vRowOff = (((sub >> 1) * 8 + r8) * FVLDT + (sub & 1) * 4) * 4;

    const int q0 = blockIdx.x * 128;
    const int h  = blockIdx.y;
    const int b  = blockIdx.z;
    const float scale = 0.03125f * 1.44269504089f;   // log2(e)/sqrt(1024)
    const size_t base  = (size_t)b * LL * EE + (size_t)h * DD;         // Q/K
    const size_t baseV = (size_t)b * EE * LL + (size_t)(h * DD) * LL;  // Vt

    auto load_kv = [&](int buf, int kt) {
        const int r = tid >> 2;              // 0..63 (K: key row; V: d row)
        const float* ksrc = Kg + base + (size_t)(kt + r) * EE;
        const float* vsrc = Vt + baseV + (size_t)r * LL + kt;
        const uint32_t kdst = smKs + (buf * 64 * FKLD + r * FKLD) * 4;
        const uint32_t vdst = smVs + (buf * 64 * FVLDT + r * FVLDT) * 4;
        #pragma unroll
        for (int u = 0; u < 4; u++) {
            const int c = ((tid & 3) + u * 4) * 4;
            cp16(kdst + c * 4, ksrc + c);
            cp16(vdst + c * 4, vsrc + c);
        }
        cp_commit();
    };

    load_kv(0, 0);

    // Load Q tile (log2e-folded scale + tf32 round), q-major
    {
        const int r  = tid >> 1;
        const int c0 = (tid & 1) * 32;
        const float* src = Q + base + (size_t)(q0 + r) * EE + c0;
        #pragma unroll
        for (int u = 0; u < 8; u++) {
            float4 v = *(const float4*)(src + u * 4);
            Qs[r * FQLD + c0 + u * 4 + 0] = f2tf32f(v.x * scale);
            Qs[r * FQLD + c0 + u * 4 + 1] = f2tf32f(v.y * scale);
            Qs[r * FQLD + c0 + u * 4 + 2] = f2tf32f(v.z * scale);
            Qs[r * FQLD + c0 + u * 4 + 3] = f2tf32f(v.w * scale);
        }
    }

    float l_i[2] = {0.0f, 0.0f};
    float o[8][4];
    #pragma unroll
    for (int nt = 0; nt < 8; nt++)
        #pragma unroll
        for (int r = 0; r < 4; r++) o[nt][r] = 0.0f;

    const int NT = LL / 64;
    for (int it = 0; it < NT; it++) {
        cp_wait<0>();
        __syncthreads();
        if (it + 1 < NT) load_kv((it + 1) & 1, (it + 1) * 64);

        const uint32_t kBuf = smKs + (it & 1) * 64 * FKLD * 4;
        const uint32_t vBuf = smVs + (it & 1) * 64 * FVLDT * 4;

        // S = Q @ K^T  (log2-domain energies; ldmatrix fragments)
        float s[8][4];
        #pragma unroll
        for (int nt = 0; nt < 8; nt++)
            #pragma unroll
            for (int r = 0; r < 4; r++) s[nt][r] = 0.0f;

        #pragma unroll
        for (int ks = 0; ks < 8; ks++) {
            const int d8 = ks * 8;
            uint32_t a0, a1, a2, a3;
            LDSM4(a0, a1, a2, a3, qA + d8 * 4);
            #pragma unroll
            for (int p = 0; p < 4; p++) {
                uint32_t b0A, b1A, b0B, b1B;
                LDSM4(b0A, b1A, b0B, b1B,
                      kBuf + p * 16 * FKLD * 4 + kRowOff + d8 * 4);
                mma_tf32_m16n8k8(s[2 * p],     a0, a1, a2, a3, b0A, b1A);
                mma_tf32_m16n8k8(s[2 * p + 1], a0, a1, a2, a3, b0B, b1B);
            }
        }

        // Fixed-max softmax: p = 2^s directly (no max, no corrections).
        float ls0 = 0.0f, ls1 = 0.0f;
        #pragma unroll
        for (int nt = 0; nt < 8; nt++) {
            s[nt][0] = ex2f(s[nt][0]);
            s[nt][1] = ex2f(s[nt][1]);
            s[nt][2] = ex2f(s[nt][2]);
            s[nt][3] = ex2f(s[nt][3]);
            ls0 += s[nt][0] + s[nt][1];
            ls1 += s[nt][2] + s[nt][3];
        }
        #pragma unroll
        for (int off = 1; off < 4; off <<= 1) {
            ls0 += __shfl_xor_sync(0xffffffffu, ls0, off);
            ls1 += __shfl_xor_sync(0xffffffffu, ls1, off);
        }
        l_i[0] += ls0;
        l_i[1] += ls1;

        // O += P @ V. P A-fragments by shuffle; V B-fragments by ldmatrix.
        const int src0 = (g << 2) | (t >> 1);
        const bool odd = (t & 1);
        #pragma unroll
        for (int ks = 0; ks < 8; ks++) {
            float p0 = __shfl_sync(0xffffffffu, s[ks][0], src0);
            float p1 = __shfl_sync(0xffffffffu, s[ks][1], src0);
            float p2 = __shfl_sync(0xffffffffu, s[ks][2], src0);
            float p3 = __shfl_sync(0xffffffffu, s[ks][3], src0);
            float r0 = __shfl_sync(0xffffffffu, s[ks][0], src0 + 2);
            float r1 = __shfl_sync(0xffffffffu, s[ks][1], src0 + 2);
            float r2 = __shfl_sync(0xffffffffu, s[ks][2], src0 + 2);
            float r3 = __shfl_sync(0xffffffffu, s[ks][3], src0 + 2);
            uint32_t a0 = f2tf32(odd ? p1 : p0);
            uint32_t a1 = f2tf32(odd ? p3 : p2);
            uint32_t a2 = f2tf32(odd ? r1 : r0);
            uint32_t a3 = f2tf32(odd ? r3 : r2);
            const int key8 = ks * 8;
            #pragma unroll
            for (int pp = 0; pp < 4; pp++) {
                uint32_t v0, v1, v2, v3;
                LDSM4(v0, v1, v2, v3,
                      vBuf + pp * 16 * FVLDT * 4 + vRowOff + key8 * 4);
                mma_tf32_m16n8k8(o[2 * pp],     a0, a1, a2, a3, v0, v1);
                mma_tf32_m16n8k8(o[2 * pp + 1], a0, a1, a2, a3, v2, v3);
            }
        }
    }

    // Write normalized output directly as bf16 hi/lo splits
    const float inv0 = 1.0f / l_i[0];
    const float inv1 = 1.0f / l_i[1];
    #pragma unroll
    for (int nt = 0; nt < 8; nt++) {
        const size_t off0 = base + (size_t)(q0 + qw + g) * EE + nt * 8 + 2 * t;
        const size_t off1 = base + (size_t)(q0 + qw + g + 8) * EE + nt * 8 + 2 * t;
        float v00 = o[nt][0] * inv0, v01 = o[nt][1] * inv0;
        float v10 = o[nt][2] * inv1, v11 = o[nt][3] * inv1;
        __nv_bfloat16 h00 = __float2bfloat16(v00), h01 = __float2bfloat16(v01);
        __nv_bfloat16 h10 = __float2bfloat16(v10), h11 = __float2bfloat16(v11);
        __nv_bfloat16 l00 = __float2bfloat16(v00 - __bfloat162float(h00));
        __nv_bfloat16 l01 = __float2bfloat16(v01 - __bfloat162float(h01));
        __nv_bfloat16 l10 = __float2bfloat16(v10 - __bfloat162float(h10));
        __nv_bfloat16 l11 = __float2bfloat16(v11 - __bfloat162float(h11));
        *(__nv_bfloat162*)&Oh[off0] = __nv_bfloat162{h00, h01};
        *(__nv_bfloat162*)&Ol[off0] = __nv_bfloat162{l00, l01};
        *(__nv_bfloat162*)&Oh[off1] = __nv_bfloat162{h10, h11};
        *(__nv_bfloat162*)&Ol[off1] = __nv_bfloat162{l10, l11};
    }
}

// ----------------------------------------------------------------------------
extern "C" void kernel_launch(void* const* d_in, const int* in_sizes, int n_in,
                              void* d_out, int out_size)
{
    const float* x  = (const float*)d_in[0];
    const float* Wq = (const float*)d_in[1];
    const float* Wk = (const float*)d_in[2];
    const float* Wv = (const float*)d_in[3];
    const float* Wo = (const float*)d_in[4];
    const float* bo = (const float*)d_in[5];
    float* out = (float*)d_out;

    float* QKV;
    __nv_bfloat16 *Ah, *Al, *Wh, *Wl;
    cudaGetSymbolAddress((void**)&QKV, g_QKV);
    cudaGetSymbolAddress((void**)&Ah, g_Ah);
    cudaGetSymbolAddress((void**)&Al, g_Al);
    cudaGetSymbolAddress((void**)&Wh, g_Wh);
    cudaGetSymbolAddress((void**)&Wl, g_Wl);

    const int nx2 = MM * EE / 2;

    size_t gsmem = 2 * STAGE_B * sizeof(__nv_bfloat16);   // 81,920 B
    cudaFuncSetAttribute(gemm_bf16x3, cudaFuncAttributeMaxDynamicSharedMemorySize,
                         (int)gsmem);
    size_t fsmem = (128 * FQLD + 2 * 64 * FKLD + 2 * 64 * FVLDT) * sizeof(float);
    cudaFuncSetAttribute(flash_mma, cudaFuncAttributeMaxDynamicSharedMemorySize,
                         (int)fsmem);                      // 104,448 B

    // 1) split all 4 weights (transposed) in one launch
    dim3 gw(EE / 32, EE / 32, 4);
    split_w4<<<gw, 256>>>(Wq, Wk, Wv, Wo, Wh, Wl, EE, EE);

    // 2) split x
    split_bf16<<<(nx2 + 255) / 256, 256>>>((const float2*)x,
        (__nv_bfloat162*)Ah, (__nv_bfloat162*)Al, nx2);

    // 3) fused Q/K/V projection (V written transposed: tsel=2)
    dim3 gqkv(3 * (EE / 128), MM / 128);    // (24, 64)
    gemm_bf16x3<<<gqkv, 256, gsmem>>>(Ah, Al, Wh, Wl, nullptr, QKV,
                                      MM, EE, EE, EE / 128, 2);

    // 4) attention; writes O directly as bf16 hi/lo into Ah/Al
    dim3 ga(LL / 128, HH, BB);              // (16, 16, 4)
    flash_mma<<<ga, 256, fsmem>>>(QKV, QKV + (size_t)MM * EE,
                                  QKV + 2 * (size_t)MM * EE, Ah, Al);

    // 5) output projection (weight slot 3) + bias
    dim3 go(EE / 128, MM / 128);            // (8, 64)
    gemm_bf16x3<<<go, 256, gsmem>>>(Ah, Al,
        Wh + 3 * (size_t)EE * EE, Wl + 3 * (size_t)EE * EE,
        bo, out, MM, EE, EE, EE / 128, -1);
}

// round 17
// speedup vs baseline: 1.0219x; 1.0219x over previous
#include <cuda_runtime.h>
#include <cuda_bf16.h>
#include <cstdint>

// Problem constants
#define BB 4
#define LL 2048
#define EE 1024
#define HH 16
#define DD 64
#define MM (BB * LL)   // 8192 rows

// Scratch (allocation-free rule: __device__ globals)
__device__ float g_QKV[3 * MM * EE];                 // Q,K key-major; V d-major [B][E][L]
__device__ __nv_bfloat16 g_Ah[MM * EE];              // x-split, then O-split
__device__ __nv_bfloat16 g_Al[MM * EE];
__device__ __nv_bfloat16 g_Wh[4 * EE * EE];          // Wq,Wk,Wv,Wo hi
__device__ __nv_bfloat16 g_Wl[4 * EE * EE];          // lo

// ----------------------------------------------------------------------------
// helpers
// ----------------------------------------------------------------------------
__device__ __forceinline__ uint32_t f2tf32(float a) {
    uint32_t r;
    asm("cvt.rna.tf32.f32 %0, %1;" : "=r"(r) : "f"(a));
    return r;
}
__device__ __forceinline__ float f2tf32f(float a) {
    return __uint_as_float(f2tf32(a));
}
__device__ __forceinline__ float ex2f(float x) {
    float r;
    asm("ex2.approx.ftz.f32 %0, %1;" : "=f"(r) : "f"(x));
    return r;
}

__device__ __forceinline__ void mma_tf32_m16n8k8(
    float d[4], uint32_t a0, uint32_t a1, uint32_t a2, uint32_t a3,
    uint32_t b0, uint32_t b1)
{
    asm volatile(
        "mma.sync.aligned.m16n8k8.row.col.f32.tf32.tf32.f32 "
        "{%0,%1,%2,%3}, {%4,%5,%6,%7}, {%8,%9}, {%0,%1,%2,%3};"
        : "+f"(d[0]), "+f"(d[1]), "+f"(d[2]), "+f"(d[3])
        : "r"(a0), "r"(a1), "r"(a2), "r"(a3), "r"(b0), "r"(b1));
}

__device__ __forceinline__ void mma_bf16_m16n8k16(
    float d[4], uint32_t a0, uint32_t a1, uint32_t a2, uint32_t a3,
    uint32_t b0, uint32_t b1)
{
    asm volatile(
        "mma.sync.aligned.m16n8k16.row.col.f32.bf16.bf16.f32 "
        "{%0,%1,%2,%3}, {%4,%5,%6,%7}, {%8,%9}, {%0,%1,%2,%3};"
        : "+f"(d[0]), "+f"(d[1]), "+f"(d[2]), "+f"(d[3])
        : "r"(a0), "r"(a1), "r"(a2), "r"(a3), "r"(b0), "r"(b1));
}

#define LDSM4(r0, r1, r2, r3, addr) \
    asm volatile("ldmatrix.sync.aligned.m8n8.x4.shared.b16 {%0,%1,%2,%3}, [%4];" \
                 : "=r"(r0), "=r"(r1), "=r"(r2), "=r"(r3) : "r"(addr))

__device__ __forceinline__ void cp16(uint32_t smem_dst, const void* gsrc) {
    asm volatile("cp.async.cg.shared.global [%0], [%1], 16;\n"
                 :: "r"(smem_dst), "l"(gsrc));
}
__device__ __forceinline__ void cp_commit() {
    asm volatile("cp.async.commit_group;\n");
}
template <int N> __device__ __forceinline__ void cp_wait() {
    asm volatile("cp.async.wait_group %0;\n" :: "n"(N));
}
__device__ __forceinline__ uint32_t smem_u32(const void* p) {
    return (uint32_t)__cvta_generic_to_shared(p);
}

// ----------------------------------------------------------------------------
// Elementwise split fp32 -> (bf16 hi, bf16 lo). n2 = element count / 2.
// ----------------------------------------------------------------------------
__global__ __launch_bounds__(256) void split_bf16(
    const float2* __restrict__ in, __nv_bfloat162* __restrict__ hi,
    __nv_bfloat162* __restrict__ lo, int n2)
{
    int i = blockIdx.x * blockDim.x + threadIdx.x;
    if (i >= n2) return;
    float2 v = in[i];
    __nv_bfloat16 hx = __float2bfloat16(v.x);
    __nv_bfloat16 hy = __float2bfloat16(v.y);
    __nv_bfloat16 lx = __float2bfloat16(v.x - __bfloat162float(hx));
    __nv_bfloat16 ly = __float2bfloat16(v.y - __bfloat162float(hy));
    hi[i] = __nv_bfloat162{hx, hy};
    lo[i] = __nv_bfloat162{lx, ly};
}

// ----------------------------------------------------------------------------
// Split + transpose all 4 weights: W fp32 [K][N] -> hi/lo bf16 [N][K].
// ----------------------------------------------------------------------------
__global__ __launch_bounds__(256) void split_w4(
    const float* __restrict__ W0, const float* __restrict__ W1,
    const float* __restrict__ W2, const float* __restrict__ W3,
    __nv_bfloat16* __restrict__ hi, __nv_bfloat16* __restrict__ lo,
    int K, int N)
{
    __shared__ float tile[32][33];
    const int z = blockIdx.z;
    const float* in = (z == 0) ? W0 : (z == 1) ? W1 : (z == 2) ? W2 : W3;
    __nv_bfloat16* hz = hi + (size_t)z * K * N;
    __nv_bfloat16* lz = lo + (size_t)z * K * N;

    const int k0 = blockIdx.y * 32;
    const int n0 = blockIdx.x * 32;
    const int tx = threadIdx.x & 31;
    const int ty = threadIdx.x >> 5;   // 0..7

    #pragma unroll
    for (int p = 0; p < 4; p++)
        tile[ty + p * 8][tx] = in[(size_t)(k0 + ty + p * 8) * N + n0 + tx];
    __syncthreads();

    #pragma unroll
    for (int p = 0; p < 4; p++) {
        const int n = n0 + ty + p * 8;
        float v = tile[tx][ty + p * 8];
        __nv_bfloat16 h = __float2bfloat16(v);
        __nv_bfloat16 l = __float2bfloat16(v - __bfloat162float(h));
        hz[(size_t)n * K + k0 + tx] = h;
        lz[(size_t)n * K + k0 + tx] = l;
    }
}

// ----------------------------------------------------------------------------
// bf16x3 GEMM: BK=32, 2-stage cp.async, LDSM fragments, 2 CTAs/SM.
// If sel == tsel, C slice is written TRANSPOSED as [B][N][L] (d-major V).
// (unchanged from round 14)
// ----------------------------------------------------------------------------
#define GLDB 40                         // smem row stride bf16 (32 + 8 pad)
#define STAGE_B (4 * 128 * GLDB)        // bf16 elems/stage = 20480 (40,960 B)

__global__ __launch_bounds__(256, 2) void gemm_bf16x3(
    const __nv_bfloat16* __restrict__ Ah, const __nv_bfloat16* __restrict__ Al,
    const __nv_bfloat16* __restrict__ Wh, const __nv_bfloat16* __restrict__ Wl,
    const float* __restrict__ bias, float* __restrict__ C,
    int M, int N, int K, int nblk, int tsel)
{
    extern __shared__ __nv_bfloat16 gsmb[];
    const uint32_t smbase = smem_u32(gsmb);

    const int tid  = threadIdx.x;
    const int lane = tid & 31;
    const int wid  = tid >> 5;
    const int wm   = (wid >> 2) * 64;
    const int wn   = (wid & 3) * 32;
    const int g    = lane >> 2;
    const int t    = lane & 3;

    const int sel = blockIdx.x / nblk;
    const int n0  = (blockIdx.x - sel * nblk) * 128;
    const int m0  = blockIdx.y * 128;

    const __nv_bfloat16* Bh = Wh + (size_t)sel * N * K;
    const __nv_bfloat16* Bl = Wl + (size_t)sel * N * K;
    float* Cs = C + (size_t)sel * M * N;

    const int aRow = wm + (lane & 7) + ((lane >> 3) & 1) * 8;
    const int aCol = (lane >> 4) * 8;
    const int bRow = wn + (lane & 7) + (lane >> 4) * 8;
    const int bCol = ((lane >> 3) & 1) * 8;

    float acc[4][4][4];
    #pragma unroll
    for (int i = 0; i < 4; i++)
        #pragma unroll
        for (int j = 0; j < 4; j++)
            #pragma unroll
            for (int r = 0; r < 4; r++) acc[i][j][r] = 0.0f;

    const int lr = tid >> 2;          // 0..63 (2 passes of 64 rows)
    const int lc = (tid & 3) * 8;     // bf16 col of 16B chunk

    auto load_stage = [&](int stage, int k0) {
        const uint32_t s0 = smbase + stage * STAGE_B * 2;
        const uint32_t aH = s0;
        const uint32_t aL = s0 + 128 * GLDB * 2;
        const uint32_t bH = s0 + 2 * 128 * GLDB * 2;
        const uint32_t bL = bH + 128 * GLDB * 2;
        #pragma unroll
        for (int p = 0; p < 2; p++) {
            const int r = lr + p * 64;
            const uint32_t so = (r * GLDB + lc) * 2;
            const size_t ga = (size_t)(m0 + r) * K + k0 + lc;
            cp16(aH + so, Ah + ga);
            cp16(aL + so, Al + ga);
            const size_t gb = (size_t)(n0 + r) * K + k0 + lc;
            cp16(bH + so, Bh + gb);
            cp16(bL + so, Bl + gb);
        }
        cp_commit();
    };

    load_stage(0, 0);

    const int ntiles = K / 32;
    for (int kt = 0; kt < ntiles; kt++) {
        if (kt + 1 < ntiles) {
            load_stage((kt + 1) & 1, (kt + 1) * 32);
            cp_wait<1>();
        } else {
            cp_wait<0>();
        }
        __syncthreads();

        const uint32_t sSt = smbase + (kt & 1) * STAGE_B * 2;
        const uint32_t sAh = sSt;
        const uint32_t sAl = sSt + 128 * GLDB * 2;
        const uint32_t sBh = sSt + 2 * 128 * GLDB * 2;
        const uint32_t sBl = sBh + 128 * GLDB * 2;

        #pragma unroll
        for (int ks = 0; ks < 2; ks++) {
            const int kk = ks * 16;
            uint32_t ah[4][4], al[4][4];
            #pragma unroll
            for (int mt = 0; mt < 4; mt++) {
                const uint32_t off = ((aRow + mt * 16) * GLDB + kk + aCol) * 2;
                LDSM4(ah[mt][0], ah[mt][1], ah[mt][2], ah[mt][3], sAh + off);
                LDSM4(al[mt][0], al[mt][1], al[mt][2], al[mt][3], sAl + off);
            }
            uint32_t bh[4][2], bl[4][2];
            #pragma unroll
            for (int p = 0; p < 2; p++) {
                const uint32_t off = ((bRow + p * 16) * GLDB + kk + bCol) * 2;
                LDSM4(bh[2 * p][0], bh[2 * p][1], bh[2 * p + 1][0], bh[2 * p + 1][1],
                      sBh + off);
                LDSM4(bl[2 * p][0], bl[2 * p][1], bl[2 * p + 1][0], bl[2 * p + 1][1],
                      sBl + off);
            }
            #pragma unroll
            for (int mt = 0; mt < 4; mt++)
                #pragma unroll
                for (int nt = 0; nt < 4; nt++) {
                    mma_bf16_m16n8k16(acc[mt][nt], al[mt][0], al[mt][1], al[mt][2], al[mt][3],
                                      bh[nt][0], bh[nt][1]);
                    mma_bf16_m16n8k16(acc[mt][nt], ah[mt][0], ah[mt][1], ah[mt][2], ah[mt][3],
                                      bl[nt][0], bl[nt][1]);
                    mma_bf16_m16n8k16(acc[mt][nt], ah[mt][0], ah[mt][1], ah[mt][2], ah[mt][3],
                                      bh[nt][0], bh[nt][1]);
                }
        }
        __syncthreads();
    }

    // Epilogue
    if (sel == tsel) {
        // transposed store: Cs treated as [B][N][L]
        #pragma unroll
        for (int mt = 0; mt < 4; mt++) {
            const int rr = m0 + wm + mt * 16 + g;
            const int bi = rr >> 11;            // rr / LL
            const int l  = rr & 2047;           // rr % LL
            float* Vt = Cs + (size_t)bi * EE * LL;
            #pragma unroll
            for (int nt = 0; nt < 4; nt++) {
                const int c = n0 + wn + nt * 8 + 2 * t;
                Vt[(size_t)c * LL + l]           = acc[mt][nt][0];
                Vt[(size_t)(c + 1) * LL + l]     = acc[mt][nt][1];
                Vt[(size_t)c * LL + l + 8]       = acc[mt][nt][2];
                Vt[(size_t)(c + 1) * LL + l + 8] = acc[mt][nt][3];
            }
        }
    } else {
        #pragma unroll
        for (int mt = 0; mt < 4; mt++) {
            const int r0 = m0 + wm + mt * 16 + g;
            #pragma unroll
            for (int nt = 0; nt < 4; nt++) {
                const int c = n0 + wn + nt * 8 + 2 * t;
                float b0 = bias ? bias[c]     : 0.0f;
                float b1 = bias ? bias[c + 1] : 0.0f;
                *(float2*)&Cs[(size_t)r0 * N + c] =
                    make_float2(acc[mt][nt][0] + b0, acc[mt][nt][1] + b1);
                *(float2*)&Cs[(size_t)(r0 + 8) * N + c] =
                    make_float2(acc[mt][nt][2] + b0, acc[mt][nt][3] + b1);
            }
        }
    }
}

// ----------------------------------------------------------------------------
// Flash attention v3: warp m-tile doubled to m32 (256 q-rows/CTA, 8 warps),
// halving K/V fragment smem traffic per MMA (the measured binding resource).
// 1 CTA/SM (139 KB smem), launch_bounds(256,1) -> ~256 regs/thread budget.
// Q/K/V fragments via ldmatrix; fixed-max log2-domain softmax; no P smem.
// ----------------------------------------------------------------------------
#define FQLD 68
#define FKLD 68
#define FVLDT 68
#define QROWS 256

__global__ __launch_bounds__(256, 1) void flash_mma(
    const float* __restrict__ Q, const float* __restrict__ Kg,
    const float* __restrict__ Vt,
    __nv_bfloat16* __restrict__ Oh, __nv_bfloat16* __restrict__ Ol)
{
    extern __shared__ float sm[];
    float* Qs  = sm;                         // [256][FQLD]
    float* Ksb = Qs + QROWS * FQLD;          // 2 x [64][FKLD]   key-major
    float* Vsb = Ksb + 2 * 64 * FKLD;        // 2 x [64][FVLDT]  d-major
    const uint32_t smQs = smem_u32(Qs);
    const uint32_t smKs = smem_u32(Ksb);
    const uint32_t smVs = smem_u32(Vsb);

    const int tid  = threadIdx.x;
    const int lane = tid & 31;
    const int wid  = tid >> 5;
    const int g    = lane >> 2;
    const int t    = lane & 3;
    const int qw   = wid * 32;               // warp owns 32 q-rows

    // ldmatrix lane address components
    const int r8  = lane & 7;
    const int sub = lane >> 3;               // 0..3 (matrix index)
    const uint32_t qA0 = smQs + ((qw + r8 + (sub & 1) * 8) * FQLD + (sub >> 1) * 4) * 4;
    const uint32_t qA1 = qA0 + 16 * FQLD * 4;
    const uint32_t kRowOff = ((r8 + (sub >> 1) * 8) * FKLD + (sub & 1) * 4) * 4;
    const uint32_t vRowOff = (((sub >> 1) * 8 + r8) * FVLDT + (sub & 1) * 4) * 4;

    const int q0 = blockIdx.x * QROWS;
    const int h  = blockIdx.y;
    const int b  = blockIdx.z;
    const float scale = 0.03125f * 1.44269504089f;   // log2(e)/sqrt(1024)
    const size_t base  = (size_t)b * LL * EE + (size_t)h * DD;         // Q/K
    const size_t baseV = (size_t)b * EE * LL + (size_t)(h * DD) * LL;  // Vt

    auto load_kv = [&](int buf, int kt) {
        const int r = tid >> 2;              // 0..63 (K: key row; V: d row)
        const float* ksrc = Kg + base + (size_t)(kt + r) * EE;
        const float* vsrc = Vt + baseV + (size_t)r * LL + kt;
        const uint32_t kdst = smKs + (buf * 64 * FKLD + r * FKLD) * 4;
        const uint32_t vdst = smVs + (buf * 64 * FVLDT + r * FVLDT) * 4;
        #pragma unroll
        for (int u = 0; u < 4; u++) {
            const int c = ((tid & 3) + u * 4) * 4;
            cp16(kdst + c * 4, ksrc + c);
            cp16(vdst + c * 4, vsrc + c);
        }
        cp_commit();
    };

    load_kv(0, 0);

    // Load Q tile (log2e-folded scale + tf32 round), q-major; 1 row/thread
    {
        const float* src = Q + base + (size_t)(q0 + tid) * EE;
        #pragma unroll
        for (int u = 0; u < 16; u++) {
            float4 v = *(const float4*)(src + u * 4);
            Qs[tid * FQLD + u * 4 + 0] = f2tf32f(v.x * scale);
            Qs[tid * FQLD + u * 4 + 1] = f2tf32f(v.y * scale);
            Qs[tid * FQLD + u * 4 + 2] = f2tf32f(v.z * scale);
            Qs[tid * FQLD + u * 4 + 3] = f2tf32f(v.w * scale);
        }
    }

    float l_i[2][2] = {{0.0f, 0.0f}, {0.0f, 0.0f}};
    float o[2][8][4];
    #pragma unroll
    for (int mt = 0; mt < 2; mt++)
        #pragma unroll
        for (int nt = 0; nt < 8; nt++)
            #pragma unroll
            for (int r = 0; r < 4; r++) o[mt][nt][r] = 0.0f;

    const int NT = LL / 64;
    for (int it = 0; it < NT; it++) {
        cp_wait<0>();
        __syncthreads();
        if (it + 1 < NT) load_kv((it + 1) & 1, (it + 1) * 64);

        const uint32_t kBuf = smKs + (it & 1) * 64 * FKLD * 4;
        const uint32_t vBuf = smVs + (it & 1) * 64 * FVLDT * 4;

        // S = Q @ K^T  (log2-domain energies)
        float s[2][8][4];
        #pragma unroll
        for (int mt = 0; mt < 2; mt++)
            #pragma unroll
            for (int nt = 0; nt < 8; nt++)
                #pragma unroll
                for (int r = 0; r < 4; r++) s[mt][nt][r] = 0.0f;

        #pragma unroll
        for (int ks = 0; ks < 8; ks++) {
            const int d8 = ks * 8;
            uint32_t a00, a01, a02, a03, a10, a11, a12, a13;
            LDSM4(a00, a01, a02, a03, qA0 + d8 * 4);
            LDSM4(a10, a11, a12, a13, qA1 + d8 * 4);
            #pragma unroll
            for (int p = 0; p < 4; p++) {
                uint32_t b0A, b1A, b0B, b1B;
                LDSM4(b0A, b1A, b0B, b1B,
                      kBuf + p * 16 * FKLD * 4 + kRowOff + d8 * 4);
                mma_tf32_m16n8k8(s[0][2 * p],     a00, a01, a02, a03, b0A, b1A);
                mma_tf32_m16n8k8(s[0][2 * p + 1], a00, a01, a02, a03, b0B, b1B);
                mma_tf32_m16n8k8(s[1][2 * p],     a10, a11, a12, a13, b0A, b1A);
                mma_tf32_m16n8k8(s[1][2 * p + 1], a10, a11, a12, a13, b0B, b1B);
            }
        }

        // Fixed-max softmax: p = 2^s directly.
        #pragma unroll
        for (int mt = 0; mt < 2; mt++) {
            float ls0 = 0.0f, ls1 = 0.0f;
            #pragma unroll
            for (int nt = 0; nt < 8; nt++) {
                s[mt][nt][0] = ex2f(s[mt][nt][0]);
                s[mt][nt][1] = ex2f(s[mt][nt][1]);
                s[mt][nt][2] = ex2f(s[mt][nt][2]);
                s[mt][nt][3] = ex2f(s[mt][nt][3]);
                ls0 += s[mt][nt][0] + s[mt][nt][1];
                ls1 += s[mt][nt][2] + s[mt][nt][3];
            }
            #pragma unroll
            for (int off = 1; off < 4; off <<= 1) {
                ls0 += __shfl_xor_sync(0xffffffffu, ls0, off);
                ls1 += __shfl_xor_sync(0xffffffffu, ls1, off);
            }
            l_i[mt][0] += ls0;
            l_i[mt][1] += ls1;
        }

        // O += P @ V. P A-fragments by shuffle; V B-fragments by ldmatrix.
        const int src0 = (g << 2) | (t >> 1);
        const bool odd = (t & 1);
        #pragma unroll
        for (int ks = 0; ks < 8; ks++) {
            uint32_t a[2][4];
            #pragma unroll
            for (int mt = 0; mt < 2; mt++) {
                float p0 = __shfl_sync(0xffffffffu, s[mt][ks][0], src0);
                float p1 = __shfl_sync(0xffffffffu, s[mt][ks][1], src0);
                float p2 = __shfl_sync(0xffffffffu, s[mt][ks][2], src0);
                float p3 = __shfl_sync(0xffffffffu, s[mt][ks][3], src0);
                float r0 = __shfl_sync(0xffffffffu, s[mt][ks][0], src0 + 2);
                float r1 = __shfl_sync(0xffffffffu, s[mt][ks][1], src0 + 2);
                float r2 = __shfl_sync(0xffffffffu, s[mt][ks][2], src0 + 2);
                float r3 = __shfl_sync(0xffffffffu, s[mt][ks][3], src0 + 2);
                a[mt][0] = f2tf32(odd ? p1 : p0);
                a[mt][1] = f2tf32(odd ? p3 : p2);
                a[mt][2] = f2tf32(odd ? r1 : r0);
                a[mt][3] = f2tf32(odd ? r3 : r2);
            }
            const int key8 = ks * 8;
            #pragma unroll
            for (int pp = 0; pp < 4; pp++) {
                uint32_t v0, v1, v2, v3;
                LDSM4(v0, v1, v2, v3,
                      vBuf + pp * 16 * FVLDT * 4 + vRowOff + key8 * 4);
                mma_tf32_m16n8k8(o[0][2 * pp],     a[0][0], a[0][1], a[0][2], a[0][3], v0, v1);
                mma_tf32_m16n8k8(o[0][2 * pp + 1], a[0][0], a[0][1], a[0][2], a[0][3], v2, v3);
                mma_tf32_m16n8k8(o[1][2 * pp],     a[1][0], a[1][1], a[1][2], a[1][3], v0, v1);
                mma_tf32_m16n8k8(o[1][2 * pp + 1], a[1][0], a[1][1], a[1][2], a[1][3], v2, v3);
            }
        }
    }

    // Write normalized output directly as bf16 hi/lo splits
    #pragma unroll
    for (int mt = 0; mt < 2; mt++) {
        const float inv0 = 1.0f / l_i[mt][0];
        const float inv1 = 1.0f / l_i[mt][1];
        const int rbase = q0 + qw + mt * 16;
        #pragma unroll
        for (int nt = 0; nt < 8; nt++) {
            const size_t off0 = base + (size_t)(rbase + g) * EE + nt * 8 + 2 * t;
            const size_t off1 = base + (size_t)(rbase + g + 8) * EE + nt * 8 + 2 * t;
            float v00 = o[mt][nt][0] * inv0, v01 = o[mt][nt][1] * inv0;
            float v10 = o[mt][nt][2] * inv1, v11 = o[mt][nt][3] * inv1;
            __nv_bfloat16 h00 = __float2bfloat16(v00), h01 = __float2bfloat16(v01);
            __nv_bfloat16 h10 = __float2bfloat16(v10), h11 = __float2bfloat16(v11);
            __nv_bfloat16 l00 = __float2bfloat16(v00 - __bfloat162float(h00));
            __nv_bfloat16 l01 = __float2bfloat16(v01 - __bfloat162float(h01));
            __nv_bfloat16 l10 = __float2bfloat16(v10 - __bfloat162float(h10));
            __nv_bfloat16 l11 = __float2bfloat16(v11 - __bfloat162float(h11));
            *(__nv_bfloat162*)&Oh[off0] = __nv_bfloat162{h00, h01};
            *(__nv_bfloat162*)&Ol[off0] = __nv_bfloat162{l00, l01};
            *(__nv_bfloat162*)&Oh[off1] = __nv_bfloat162{h10, h11};
            *(__nv_bfloat162*)&Ol[off1] = __nv_bfloat162{l10, l11};
        }
    }
}

// ----------------------------------------------------------------------------
extern "C" void kernel_launch(void* const* d_in, const int* in_sizes, int n_in,
                              void* d_out, int out_size)
{
    const float* x  = (const float*)d_in[0];
    const float* Wq = (const float*)d_in[1];
    const float* Wk = (const float*)d_in[2];
    const float* Wv = (const float*)d_in[3];
    const float* Wo = (const float*)d_in[4];
    const float* bo = (const float*)d_in[5];
    float* out = (float*)d_out;

    float* QKV;
    __nv_bfloat16 *Ah, *Al, *Wh, *Wl;
    cudaGetSymbolAddress((void**)&QKV, g_QKV);
    cudaGetSymbolAddress((void**)&Ah, g_Ah);
    cudaGetSymbolAddress((void**)&Al, g_Al);
    cudaGetSymbolAddress((void**)&Wh, g_Wh);
    cudaGetSymbolAddress((void**)&Wl, g_Wl);

    const int nx2 = MM * EE / 2;

    size_t gsmem = 2 * STAGE_B * sizeof(__nv_bfloat16);   // 81,920 B
    cudaFuncSetAttribute(gemm_bf16x3, cudaFuncAttributeMaxDynamicSharedMemorySize,
                         (int)gsmem);
    size_t fsmem = (QROWS * FQLD + 2 * 64 * FKLD + 2 * 64 * FVLDT) * sizeof(float);
    cudaFuncSetAttribute(flash_mma, cudaFuncAttributeMaxDynamicSharedMemorySize,
                         (int)fsmem);                      // 139,264 B

    // 1) split all 4 weights (transposed) in one launch
    dim3 gw(EE / 32, EE / 32, 4);
    split_w4<<<gw, 256>>>(Wq, Wk, Wv, Wo, Wh, Wl, EE, EE);

    // 2) split x
    split_bf16<<<(nx2 + 255) / 256, 256>>>((const float2*)x,
        (__nv_bfloat162*)Ah, (__nv_bfloat162*)Al, nx2);

    // 3) fused Q/K/V projection (V written transposed: tsel=2)
    dim3 gqkv(3 * (EE / 128), MM / 128);    // (24, 64)
    gemm_bf16x3<<<gqkv, 256, gsmem>>>(Ah, Al, Wh, Wl, nullptr, QKV,
                                      MM, EE, EE, EE / 128, 2);

    // 4) attention; writes O directly as bf16 hi/lo into Ah/Al
    dim3 ga(LL / QROWS, HH, BB);            // (8, 16, 4)
    flash_mma<<<ga, 256, fsmem>>>(QKV, QKV + (size_t)MM * EE,
                                  QKV + 2 * (size_t)MM * EE, Ah, Al);

    // 5) output projection (weight slot 3) + bias
    dim3 go(EE / 128, MM / 128);            // (8, 64)
    gemm_bf16x3<<<go, 256, gsmem>>>(Ah, Al,
        Wh + 3 * (size_t)EE * EE, Wl + 3 * (size_t)EE * EE,
        bo, out, MM, EE, EE, EE / 128, -1);
}